// round 6
// baseline (speedup 1.0000x reference)
#include <cuda_runtime.h>
#include <cuda_pipeline.h>

#define DIM 1024
#define NROWS 32        // B*T = 2*16 distinct kv rows
#define TPF 1560        // tokens per frame

// Scratch (no cudaMalloc allowed): intermediate v and final per-frame y.
__device__ float g_v[NROWS * DIM];
__device__ float g_y[NROWS * DIM];

#define SMEM_BYTES ((8 + 16) * DIM * 4)   // W tile 32KB + x tile 64KB = 96KB

// OUT[r, col] = sum_k IN[r, k] * W[col, k] + bias[col]
// IN: [32, 1024], W: [1024, 1024] row-major  (=> IN @ W^T + b)
//
// cp.async stages the block's W tile (8 cols x 1024) and x tile (16 rows x
// 1024) into smem in one bulk pipeline -- DRAM latency paid once with full
// MLP instead of per-chunk in each warp's LDG dependency chain. Compute
// runs off LDS (29-cyc latency) with a 4x4 register tile per warp and K
// split across lanes; butterfly reduce at the end.
// Block = 8 warps = 4 row-groups x 2 col-groups = 16 rows x 8 cols.
// Grid = 256 (128 col-blocks x 2 row-blocks). 96KB smem -> 2 CTA/SM.
__global__ __launch_bounds__(256, 2) void gemm32_kernel(
    const float* __restrict__ in,
    const float* __restrict__ W,
    const float* __restrict__ bias,
    float* __restrict__ out)
{
    extern __shared__ float s[];
    float* sW = s;                 // 8 cols  x 1024
    float* sX = s + 8 * DIM;       // 16 rows x 1024

    const int tid  = threadIdx.x;
    const int lane = tid & 31;
    const int warp = tid >> 5;
    const int rg   = warp & 3;               // row group within block
    const int cg   = warp >> 2;              // col group within block (0..1)
    const int cb   = blockIdx.x & 127;       // col block (8 cols each)
    const int rb   = blockIdx.x >> 7;        // row block (16 rows each)
    const int row0 = rb * 16;                // BLOCK tile base (staging)
    const int col0 = cb * 8;                 // BLOCK tile base (staging)

    // Bulk-stage W tile: rows col0..col0+7 of W, contiguous 32KB.
    const float4* Wg  = reinterpret_cast<const float4*>(W + (size_t)col0 * DIM);
    float4*       sW4 = reinterpret_cast<float4*>(sW);
    #pragma unroll
    for (int i = tid; i < 8 * DIM / 4; i += 256)
        __pipeline_memcpy_async(&sW4[i], &Wg[i], 16);

    // Bulk-stage x tile: rows row0..row0+15, contiguous 64KB.
    const float4* Xg  = reinterpret_cast<const float4*>(in + (size_t)row0 * DIM);
    float4*       sX4 = reinterpret_cast<float4*>(sX);
    #pragma unroll
    for (int i = tid; i < 16 * DIM / 4; i += 256)
        __pipeline_memcpy_async(&sX4[i], &Xg[i], 16);

    __pipeline_commit();
    __pipeline_wait_prior(0);
    __syncthreads();

    float acc[4][4];
    #pragma unroll
    for (int r = 0; r < 4; r++)
        #pragma unroll
        for (int c = 0; c < 4; c++) acc[r][c] = 0.0f;

    #pragma unroll
    for (int ch = 0; ch < 8; ch++) {
        const int k = ch * 128 + lane * 4;
        float4 w[4], x[4];
        #pragma unroll
        for (int c = 0; c < 4; c++)
            w[c] = *reinterpret_cast<const float4*>(&sW[(cg * 4 + c) * DIM + k]);
        #pragma unroll
        for (int r = 0; r < 4; r++)
            x[r] = *reinterpret_cast<const float4*>(&sX[(rg * 4 + r) * DIM + k]);
        #pragma unroll
        for (int r = 0; r < 4; r++)
            #pragma unroll
            for (int c = 0; c < 4; c++)
                acc[r][c] += x[r].x * w[c].x + x[r].y * w[c].y
                           + x[r].z * w[c].z + x[r].w * w[c].w;
    }

    // Butterfly-reduce the 16 accumulators across lanes.
    #pragma unroll
    for (int off = 16; off; off >>= 1)
        #pragma unroll
        for (int r = 0; r < 4; r++)
            #pragma unroll
            for (int c = 0; c < 4; c++)
                acc[r][c] += __shfl_xor_sync(0xffffffffu, acc[r][c], off);

    // Lane (r*4 + c), lanes 0..15, writes element
    // (row0 + rg*4 + r, col0 + cg*4 + c)  -- warp sub-offsets INCLUDED.
    float res = 0.0f;
    #pragma unroll
    for (int r = 0; r < 4; r++)
        #pragma unroll
        for (int c = 0; c < 4; c++)
            if (lane == r * 4 + c) res = acc[r][c];

    if (lane < 16) {
        const int r = lane >> 2, c = lane & 3;
        const int grow = row0 + rg * 4 + r;
        const int gcol = col0 + cg * 4 + c;
        out[grow * DIM + gcol] = res + bias[gcol];
    }
}

// Broadcast y[frame, :] (1024 fp32 = 256 float4) to all 1560 rows of the frame.
// Source value is loop-invariant per thread -> pure coalesced streaming stores.
__global__ __launch_bounds__(256) void bcast_kernel(
    const float4* __restrict__ y4,
    float4* __restrict__ out4)
{
    const int f   = blockIdx.y;                  // frame 0..31
    const int tid = threadIdx.x;
    const float4 val = y4[f * 256 + tid];

    const int per_frame = TPF * 256;             // 399,360 float4 per frame
    const long base = (long)f * per_frame;
    const int stride = gridDim.x * 256;

    for (int i = blockIdx.x * 256 + tid; i < per_frame; i += stride) {
        __stcs(&out4[base + i], val);            // streaming store: don't churn L2
    }
}

extern "C" void kernel_launch(void* const* d_in, const int* in_sizes, int n_in,
                              void* d_out, int out_size)
{
    // metadata order: x, c, Wq, bq, Wk, bk, Wv, bv, Wo, bo
    // softmax over a length-1 kv axis is identically 1 -> x/Wq/bq/Wk/bk unused.
    const float* c  = (const float*)d_in[1];
    const float* Wv = (const float*)d_in[6];
    const float* bv = (const float*)d_in[7];
    const float* Wo = (const float*)d_in[8];
    const float* bo = (const float*)d_in[9];
    float* out = (float*)d_out;

    void* vptr = nullptr;
    void* yptr = nullptr;
    cudaGetSymbolAddress(&vptr, g_v);
    cudaGetSymbolAddress(&yptr, g_y);
    float* v = (float*)vptr;
    float* y = (float*)yptr;

    cudaFuncSetAttribute(gemm32_kernel,
                         cudaFuncAttributeMaxDynamicSharedMemorySize, SMEM_BYTES);

    // v = c @ Wv^T + bv        (32 x 1024)
    gemm32_kernel<<<256, 256, SMEM_BYTES>>>(c, Wv, bv, v);
    // y = v @ Wo^T + bo        (32 x 1024)
    gemm32_kernel<<<256, 256, SMEM_BYTES>>>(v, Wo, bo, y);
    // out[b, t*1560+i, :] = y[b,t,:]   (204 MB broadcast store)
    bcast_kernel<<<dim3(65, 32), 256>>>((const float4*)y, (float4*)out);

    (void)in_sizes; (void)n_in; (void)out_size;
}

// round 7
// speedup vs baseline: 1.0378x; 1.0378x over previous
#include <cuda_runtime.h>
#include <cuda_pipeline.h>

#define DIM 1024
#define NROWS 32        // B*T = 2*16 distinct kv rows
#define TPF 1560        // tokens per frame

// Scratch (no cudaMalloc allowed): intermediate v and final per-frame y.
__device__ float g_v[NROWS * DIM];
__device__ float g_y[NROWS * DIM];

#define KCH 256                               // K per pipeline chunk
#define STAGE_FLOATS ((8 + 16) * KCH)         // 6144 floats = 24KB per stage
#define SMEM_BYTES (2 * STAGE_FLOATS * 4)     // 2-stage ring = 48KB

// OUT[r, col] = sum_k IN[r, k] * W[col, k] + bias[col]
// IN: [32, 1024], W: [1024, 1024] row-major  (=> IN @ W^T + b)
//
// 2-stage cp.async pipeline over 4 K-chunks of 256: chunk ch+1 streams into
// the alternate smem stage while chunk ch is computed from LDS. Only chunk
// 0's latency is exposed. 48KB smem -> 3-4 CTAs/SM for latency hiding.
// Block = 8 warps = 4 row-groups x 2 col-groups = 16 rows x 8 cols.
// Grid = 256 (128 col-blocks x 2 row-blocks).
__global__ __launch_bounds__(256) void gemm32_kernel(
    const float* __restrict__ in,
    const float* __restrict__ W,
    const float* __restrict__ bias,
    float* __restrict__ out)
{
    extern __shared__ float s[];

    const int tid  = threadIdx.x;
    const int lane = tid & 31;
    const int warp = tid >> 5;
    const int rg   = warp & 3;               // row group within block
    const int cg   = warp >> 2;              // col group within block (0..1)
    const int cb   = blockIdx.x & 127;       // col block (8 cols each)
    const int rb   = blockIdx.x >> 7;        // row block (16 rows each)
    const int row0 = rb * 16;                // block tile base
    const int col0 = cb * 8;                 // block tile base

    const float4* Wg = reinterpret_cast<const float4*>(W + (size_t)col0 * DIM);
    const float4* Xg = reinterpret_cast<const float4*>(in + (size_t)row0 * DIM);

    // Stage chunk `ch` (k in [ch*256, ch*256+256)) into ring stage `st`.
    auto stage_chunk = [&](int ch, int st) {
        float4* sW4 = reinterpret_cast<float4*>(s + st * STAGE_FLOATS);
        float4* sX4 = sW4 + 8 * (KCH / 4);   // after 8x256 W floats
        const int k4 = ch * (KCH / 4);       // float4 offset into a row
        // W tile: 8 rows x 64 float4 = 512; thread does f = tid, tid+256.
        #pragma unroll
        for (int f = tid; f < 8 * 64; f += 256) {
            int c = f >> 6, j = f & 63;
            __pipeline_memcpy_async(&sW4[f], &Wg[(size_t)c * 256 + k4 + j], 16);
        }
        // X tile: 16 rows x 64 float4 = 1024; thread does 4.
        #pragma unroll
        for (int f = tid; f < 16 * 64; f += 256) {
            int r = f >> 6, j = f & 63;
            __pipeline_memcpy_async(&sX4[f], &Xg[(size_t)r * 256 + k4 + j], 16);
        }
        __pipeline_commit();
    };

    float acc[4][4];
    #pragma unroll
    for (int r = 0; r < 4; r++)
        #pragma unroll
        for (int c = 0; c < 4; c++) acc[r][c] = 0.0f;

    stage_chunk(0, 0);

    #pragma unroll
    for (int ch = 0; ch < 4; ch++) {
        const int st = ch & 1;
        if (ch < 3) stage_chunk(ch + 1, st ^ 1);
        __pipeline_wait_prior(ch < 3 ? 1 : 0);   // chunk ch has landed
        __syncthreads();

        const float* sW = s + st * STAGE_FLOATS;          // [8][256]
        const float* sX = sW + 8 * KCH;                   // [16][256]
        #pragma unroll
        for (int half = 0; half < 2; half++) {
            const int k = half * 128 + lane * 4;
            float4 w[4], x[4];
            #pragma unroll
            for (int c = 0; c < 4; c++)
                w[c] = *reinterpret_cast<const float4*>(&sW[(cg * 4 + c) * KCH + k]);
            #pragma unroll
            for (int r = 0; r < 4; r++)
                x[r] = *reinterpret_cast<const float4*>(&sX[(rg * 4 + r) * KCH + k]);
            #pragma unroll
            for (int r = 0; r < 4; r++)
                #pragma unroll
                for (int c = 0; c < 4; c++)
                    acc[r][c] += x[r].x * w[c].x + x[r].y * w[c].y
                               + x[r].z * w[c].z + x[r].w * w[c].w;
        }
        __syncthreads();   // stage st fully consumed before it's refilled
    }

    // Butterfly-reduce the 16 accumulators across lanes.
    #pragma unroll
    for (int off = 16; off; off >>= 1)
        #pragma unroll
        for (int r = 0; r < 4; r++)
            #pragma unroll
            for (int c = 0; c < 4; c++)
                acc[r][c] += __shfl_xor_sync(0xffffffffu, acc[r][c], off);

    // Lane (r*4 + c), lanes 0..15, writes (row0 + rg*4 + r, col0 + cg*4 + c).
    float res = 0.0f;
    #pragma unroll
    for (int r = 0; r < 4; r++)
        #pragma unroll
        for (int c = 0; c < 4; c++)
            if (lane == r * 4 + c) res = acc[r][c];

    if (lane < 16) {
        const int r = lane >> 2, c = lane & 3;
        const int grow = row0 + rg * 4 + r;
        const int gcol = col0 + cg * 4 + c;
        out[grow * DIM + gcol] = res + bias[gcol];
    }
}

// Broadcast y[frame, :] (1024 fp32 = 256 float4) to all 1560 rows of the frame.
// Source value is loop-invariant per thread -> pure coalesced streaming stores.
__global__ __launch_bounds__(256) void bcast_kernel(
    const float4* __restrict__ y4,
    float4* __restrict__ out4)
{
    const int f   = blockIdx.y;                  // frame 0..31
    const int tid = threadIdx.x;
    const float4 val = y4[f * 256 + tid];

    const int per_frame = TPF * 256;             // 399,360 float4 per frame
    const long base = (long)f * per_frame;
    const int stride = gridDim.x * 256;

    for (int i = blockIdx.x * 256 + tid; i < per_frame; i += stride) {
        __stcs(&out4[base + i], val);            // streaming store: don't churn L2
    }
}

extern "C" void kernel_launch(void* const* d_in, const int* in_sizes, int n_in,
                              void* d_out, int out_size)
{
    // metadata order: x, c, Wq, bq, Wk, bk, Wv, bv, Wo, bo
    // softmax over a length-1 kv axis is identically 1 -> x/Wq/bq/Wk/bk unused.
    const float* c  = (const float*)d_in[1];
    const float* Wv = (const float*)d_in[6];
    const float* bv = (const float*)d_in[7];
    const float* Wo = (const float*)d_in[8];
    const float* bo = (const float*)d_in[9];
    float* out = (float*)d_out;

    void* vptr = nullptr;
    void* yptr = nullptr;
    cudaGetSymbolAddress(&vptr, g_v);
    cudaGetSymbolAddress(&yptr, g_y);
    float* v = (float*)vptr;
    float* y = (float*)yptr;

    cudaFuncSetAttribute(gemm32_kernel,
                         cudaFuncAttributeMaxDynamicSharedMemorySize, SMEM_BYTES);

    // v = c @ Wv^T + bv        (32 x 1024)
    gemm32_kernel<<<256, 256, SMEM_BYTES>>>(c, Wv, bv, v);
    // y = v @ Wo^T + bo        (32 x 1024)
    gemm32_kernel<<<256, 256, SMEM_BYTES>>>(v, Wo, bo, y);
    // out[b, t*1560+i, :] = y[b,t,:]   (204 MB broadcast store)
    bcast_kernel<<<dim3(130, 32), 256>>>((const float4*)y, (float4*)out);

    (void)in_sizes; (void)n_in; (void)out_size;
}